// round 9
// baseline (speedup 1.0000x reference)
#include <cuda_runtime.h>
#include <cuda_bf16.h>
#include <cstdint>
#include <math.h>

#define N_SESS   4096
#define T_TRIALS 2048
#define NCHUNK   8        // 256 trials per chunk = two 128-trial half-scans

// Warp-per-session affine scan, dual interleaved half-scans, direct LDG.
//  - chunk = 256 trials: half A = trials [0,128), half B = [128,256)
//  - each lane: 4 trials per half at 48B stride (same wavefront cost as the
//    best 4-trial kernel; avoids the 96B-stride L1tex blowup)
//  - the two 5-level shuffle scans interleave (ILP=2) -> serial chain halved
//  - depth-1 prefetch: next chunk's 6 float4 issued before the scans
//  - __ldcs / __stcs: streaming data, keep L2 clean
__global__ __launch_bounds__(128) void qvalue_kernel(
    const float* __restrict__ inp,    // (B, T, 3)
    const float* __restrict__ araw,   // (4,)
    const float* __restrict__ kv,     // (4,)
    float* __restrict__ out)          // (B, T, 2)
{
    const int gtid = blockIdx.x * blockDim.x + threadIdx.x;
    const int warp = gtid >> 5;
    const int lane = gtid & 31;
    if (warp >= N_SESS) return;

    // am[i] = 1 - sigmoid(araw[i]),  ak[i] = sigmoid(araw[i]) * k[i]
    float am[4], ak[4];
#pragma unroll
    for (int i = 0; i < 4; i++) {
        float s = 1.0f / (1.0f + expf(-araw[i]));
        am[i] = 1.0f - s;
        ak[i] = s * kv[i];
    }

    const float4* ip = reinterpret_cast<const float4*>(inp + (size_t)warp * T_TRIALS * 3);
    float4*       op = reinterpret_cast<float4*>(out + (size_t)warp * T_TRIALS * 2);

    float sl = 0.0f, sr = 0.0f;
    const unsigned FULL = 0xFFFFFFFFu;
    const int F4CHUNK = 192;              // float4 per 256-trial chunk

    // prologue: chunk 0. half A at 3*lane, half B at 96+3*lane
    int fA = 3 * lane;
    float4 v0 = __ldcs(ip + fA),      v1 = __ldcs(ip + fA + 1),  v2 = __ldcs(ip + fA + 2);
    float4 v3 = __ldcs(ip + fA + 96), v4 = __ldcs(ip + fA + 97), v5 = __ldcs(ip + fA + 98);

#pragma unroll 1
    for (int c = 0; c < NCHUNK; c++) {
        // coefficients via SEL (inputs are exact {0,1})
        float AlA[4], BlA[4], ArA[4], BrA[4];
        float AlB[4], BlB[4], ArB[4], BrB[4];
        {
            const float clA[4] = {v0.x, v0.w, v1.z, v2.y};
            const float ooA[4] = {v0.z, v1.y, v2.x, v2.w};
            const float clB[4] = {v3.x, v3.w, v4.z, v5.y};
            const float ooB[4] = {v3.z, v4.y, v5.x, v5.w};
#pragma unroll
            for (int j = 0; j < 4; j++) {
                bool po = (ooA[j] != 0.0f), pc = (clA[j] != 0.0f);
                float tA = po ? am[0] : am[1], dA = po ? am[2] : am[3];
                float tB = po ? ak[0] : ak[1], dB = po ? ak[2] : ak[3];
                AlA[j] = pc ? tA : dA;  ArA[j] = pc ? dA : tA;
                BlA[j] = pc ? tB : dB;  BrA[j] = pc ? dB : tB;
            }
#pragma unroll
            for (int j = 0; j < 4; j++) {
                bool po = (ooB[j] != 0.0f), pc = (clB[j] != 0.0f);
                float tA = po ? am[0] : am[1], dA = po ? am[2] : am[3];
                float tB = po ? ak[0] : ak[1], dB = po ? ak[2] : ak[3];
                AlB[j] = pc ? tA : dA;  ArB[j] = pc ? dA : tA;
                BlB[j] = pc ? tB : dB;  BrB[j] = pc ? dB : tB;
            }
        }

        // input regs free: prefetch next chunk (overlaps the scans below)
        if (c + 1 < NCHUNK) {
            const int fn = (c + 1) * F4CHUNK + 3 * lane;
            v0 = __ldcs(ip + fn);      v1 = __ldcs(ip + fn + 1);  v2 = __ldcs(ip + fn + 2);
            v3 = __ldcs(ip + fn + 96); v4 = __ldcs(ip + fn + 97); v5 = __ldcs(ip + fn + 98);
        }

        // per-lane composition, both halves (trial 0 first)
        float AclA = AlA[0], BclA = BlA[0], AcrA = ArA[0], BcrA = BrA[0];
        float AclB = AlB[0], BclB = BlB[0], AcrB = ArB[0], BcrB = BrB[0];
#pragma unroll
        for (int j = 1; j < 4; j++) {
            BclA = fmaf(AlA[j], BclA, BlA[j]);  AclA = AlA[j] * AclA;
            BcrA = fmaf(ArA[j], BcrA, BrA[j]);  AcrA = ArA[j] * AcrA;
            BclB = fmaf(AlB[j], BclB, BlB[j]);  AclB = AlB[j] * AclB;
            BcrB = fmaf(ArB[j], BcrB, BrB[j]);  AcrB = ArB[j] * AcrB;
        }

        // two interleaved 5-level inclusive warp scans (ILP = 2)
#pragma unroll
        for (int d = 1; d < 32; d <<= 1) {
            float pAlA = __shfl_up_sync(FULL, AclA, d);
            float pBlA = __shfl_up_sync(FULL, BclA, d);
            float pArA = __shfl_up_sync(FULL, AcrA, d);
            float pBrA = __shfl_up_sync(FULL, BcrA, d);
            float pAlB = __shfl_up_sync(FULL, AclB, d);
            float pBlB = __shfl_up_sync(FULL, BclB, d);
            float pArB = __shfl_up_sync(FULL, AcrB, d);
            float pBrB = __shfl_up_sync(FULL, BcrB, d);
            if (lane >= d) {
                BclA = fmaf(AclA, pBlA, BclA);  AclA *= pAlA;
                BcrA = fmaf(AcrA, pBrA, BcrA);  AcrA *= pArA;
                BclB = fmaf(AclB, pBlB, BclB);  AclB *= pAlB;
                BcrB = fmaf(AcrB, pBrB, BcrB);  AcrB *= pArB;
            }
        }

        // half-A entering states; half-B entering session state from
        // half-A lane31 composition (off the regen critical path)
        float AeA_l = __shfl_up_sync(FULL, AclA, 1);
        float BeA_l = __shfl_up_sync(FULL, BclA, 1);
        float AeA_r = __shfl_up_sync(FULL, AcrA, 1);
        float BeA_r = __shfl_up_sync(FULL, BcrA, 1);
        float A31l = __shfl_sync(FULL, AclA, 31);
        float B31l = __shfl_sync(FULL, BclA, 31);
        float A31r = __shfl_sync(FULL, AcrA, 31);
        float B31r = __shfl_sync(FULL, BcrA, 31);
        float sBl = fmaf(A31l, sl, B31l);
        float sBr = fmaf(A31r, sr, B31r);

        float AeB_l = __shfl_up_sync(FULL, AclB, 1);
        float BeB_l = __shfl_up_sync(FULL, BclB, 1);
        float AeB_r = __shfl_up_sync(FULL, AcrB, 1);
        float BeB_r = __shfl_up_sync(FULL, BcrB, 1);
        if (lane == 0) {
            AeA_l = 1.0f; BeA_l = 0.0f;  AeA_r = 1.0f; BeA_r = 0.0f;
            AeB_l = 1.0f; BeB_l = 0.0f;  AeB_r = 1.0f; BeB_r = 0.0f;
        }
        float tlA = fmaf(AeA_l, sl,  BeA_l);
        float trA = fmaf(AeA_r, sr,  BeA_r);
        float tlB = fmaf(AeB_l, sBl, BeB_l);
        float trB = fmaf(AeB_r, sBr, BeB_r);

        // next session state from half-B lane31 composition
        {
            float A31bl = __shfl_sync(FULL, AclB, 31);
            float B31bl = __shfl_sync(FULL, BclB, 31);
            float A31br = __shfl_sync(FULL, AcrB, 31);
            float B31br = __shfl_sync(FULL, BcrB, 31);
            sl = fmaf(A31bl, sBl, B31bl);
            sr = fmaf(A31br, sBr, B31br);
        }

        // regenerate per-trial outputs, both halves
        const int ofbA = c * 128 + 2 * lane;        // float4 index into (T,2)
        const int ofbB = ofbA + 64;
        float4 oA0, oA1, oB0, oB1;
        tlA = fmaf(AlA[0], tlA, BlA[0]);  trA = fmaf(ArA[0], trA, BrA[0]);
        oA0.x = tlA;  oA0.y = trA;
        tlA = fmaf(AlA[1], tlA, BlA[1]);  trA = fmaf(ArA[1], trA, BrA[1]);
        oA0.z = tlA;  oA0.w = trA;
        tlA = fmaf(AlA[2], tlA, BlA[2]);  trA = fmaf(ArA[2], trA, BrA[2]);
        oA1.x = tlA;  oA1.y = trA;
        tlA = fmaf(AlA[3], tlA, BlA[3]);  trA = fmaf(ArA[3], trA, BrA[3]);
        oA1.z = tlA;  oA1.w = trA;

        tlB = fmaf(AlB[0], tlB, BlB[0]);  trB = fmaf(ArB[0], trB, BrB[0]);
        oB0.x = tlB;  oB0.y = trB;
        tlB = fmaf(AlB[1], tlB, BlB[1]);  trB = fmaf(ArB[1], trB, BrB[1]);
        oB0.z = tlB;  oB0.w = trB;
        tlB = fmaf(AlB[2], tlB, BlB[2]);  trB = fmaf(ArB[2], trB, BrB[2]);
        oB1.x = tlB;  oB1.y = trB;
        tlB = fmaf(AlB[3], tlB, BlB[3]);  trB = fmaf(ArB[3], trB, BrB[3]);
        oB1.z = tlB;  oB1.w = trB;

        __stcs(op + ofbA,     oA0);
        __stcs(op + ofbA + 1, oA1);
        __stcs(op + ofbB,     oB0);
        __stcs(op + ofbB + 1, oB1);
    }
}

extern "C" void kernel_launch(void* const* d_in, const int* in_sizes, int n_in,
                              void* d_out, int out_size) {
    const float* inp  = (const float*)d_in[0];   // (4096, 2048, 3) f32
    const float* araw = (const float*)d_in[1];   // (4,) f32
    const float* kv   = (const float*)d_in[2];   // (4,) f32
    float* out = (float*)d_out;                  // (4096, 2048, 2) f32

    // 4096 warps in 128-thread blocks -> 1024 blocks
    qvalue_kernel<<<1024, 128>>>(inp, araw, kv, out);
}

// round 10
// speedup vs baseline: 1.1679x; 1.1679x over previous
#include <cuda_runtime.h>
#include <cuda_bf16.h>
#include <cstdint>
#include <math.h>

#define N_SESS   4096
#define T_TRIALS 2048
#define FULLM    0xFFFFFFFFu

typedef unsigned long long ull;

// Blackwell packed f32x2 ops (ptxas never auto-fuses these; PTX-only)
__device__ __forceinline__ ull ffma2(ull a, ull b, ull c) {
    ull d;
    asm("fma.rn.f32x2 %0, %1, %2, %3;" : "=l"(d) : "l"(a), "l"(b), "l"(c));
    return d;
}
__device__ __forceinline__ ull fmul2(ull a, ull b) {
    ull d;
    asm("mul.rn.f32x2 %0, %1, %2;" : "=l"(d) : "l"(a), "l"(b));
    return d;
}

// Warp-per-session affine scan (R2 skeleton: 4 trials/lane, 16 chunks,
// depth-2 load pipeline) with a shrunken instruction stream:
//  - coefficient lookup: idx from the {0,1} input BIT patterns -> one LDS.128
//    per trial yields (Al, Ar, Bl, Br)
//  - all recurrence math on packed {left,right} pairs via fma/mul.f32x2
//  - packed pairs are already in (T,2) memory order -> swizzle-free stores
__global__ __launch_bounds__(128) void qvalue_kernel(
    const float* __restrict__ inp,    // (B, T, 3)
    const float* __restrict__ araw,   // (4,)
    const float* __restrict__ kv,     // (4,)
    float* __restrict__ out)          // (B, T, 2)
{
    // lut[idx] : .x = packed {Al, Ar}, .y = packed {Bl, Br}
    // idx = 2*chose_left + outcome;  alpha index: left = 3-idx, right = 3-(idx^2)
    __shared__ ulonglong2 lut[4];

    const int tid  = threadIdx.x;
    const int lane = tid & 31;
    const int warp = blockIdx.x * 4 + (tid >> 5);   // 1024 blocks * 4 warps

    if (tid < 4) {
        float sg[4];
#pragma unroll
        for (int i = 0; i < 4; i++) sg[i] = 1.0f / (1.0f + expf(-araw[i]));
        const int li = 3 - tid, ri = 3 - (tid ^ 2);
        const float Al = 1.0f - sg[li], Ar = 1.0f - sg[ri];
        const float Bl = sg[li] * kv[li], Br = sg[ri] * kv[ri];
        ull ap = (ull)__float_as_uint(Al) | ((ull)__float_as_uint(Ar) << 32);
        ull bp = (ull)__float_as_uint(Bl) | ((ull)__float_as_uint(Br) << 32);
        lut[tid] = make_ulonglong2(ap, bp);
    }
    __syncthreads();

    const float4* ip  = reinterpret_cast<const float4*>(inp + (size_t)warp * T_TRIALS * 3);
    ulonglong2*   op2 = reinterpret_cast<ulonglong2*>(out + (size_t)warp * T_TRIALS * 2);

    ull s = 0ull;                       // packed {s_left, s_right}

    // depth-2 pipeline: current chunk in v*, next in n*
    int f4 = 3 * lane;
    float4 v0 = ip[f4], v1 = ip[f4 + 1], v2 = ip[f4 + 2];
    f4 += 96;
    float4 n0 = ip[f4], n1 = ip[f4 + 1], n2 = ip[f4 + 2];

#pragma unroll 2
    for (int chunk = 0; chunk < 16; chunk++) {
        // per-trial LUT index from float bit patterns (1.0f has bit23 set)
        int idx[4];
        {
            const unsigned cb0 = __float_as_uint(v0.x), ob0 = __float_as_uint(v0.z);
            const unsigned cb1 = __float_as_uint(v0.w), ob1 = __float_as_uint(v1.y);
            const unsigned cb2 = __float_as_uint(v1.z), ob2 = __float_as_uint(v2.x);
            const unsigned cb3 = __float_as_uint(v2.y), ob3 = __float_as_uint(v2.w);
            idx[0] = (int)(((cb0 >> 22) & 2u) | ((ob0 >> 23) & 1u));
            idx[1] = (int)(((cb1 >> 22) & 2u) | ((ob1 >> 23) & 1u));
            idx[2] = (int)(((cb2 >> 22) & 2u) | ((ob2 >> 23) & 1u));
            idx[3] = (int)(((cb3 >> 22) & 2u) | ((ob3 >> 23) & 1u));
        }

        // rotate pipeline, issue loads for chunk+2 (overlap with scan)
        v0 = n0; v1 = n1; v2 = n2;
        if (chunk + 2 < 16) {
            f4 += 96;
            n0 = ip[f4]; n1 = ip[f4 + 1]; n2 = ip[f4 + 2];
        }

        // fetch packed coefficients: one LDS.128 per trial
        ull CA[4], CB[4];
#pragma unroll
        for (int j = 0; j < 4; j++) {
            ulonglong2 q = lut[idx[j]];
            CA[j] = q.x;  CB[j] = q.y;
        }

        // compose lane's 4 trials (trial 0 first): A=A2*A1, B=A2*B1+B2
        ull Ac = CA[0], Bc = CB[0];
#pragma unroll
        for (int j = 1; j < 4; j++) {
            Bc = ffma2(CA[j], Bc, CB[j]);
            Ac = fmul2(CA[j], Ac);
        }

        // 5-level inclusive warp scan on packed pairs
#pragma unroll
        for (int d = 1; d < 32; d <<= 1) {
            ull pA = __shfl_up_sync(FULLM, Ac, d);
            ull pB = __shfl_up_sync(FULLM, Bc, d);
            if (lane >= d) {
                Bc = ffma2(Ac, pB, Bc);
                Ac = fmul2(Ac, pA);
            }
        }

        // exclusive prefix -> state entering this lane's trials
        ull Ae = __shfl_up_sync(FULLM, Ac, 1);
        ull Be = __shfl_up_sync(FULLM, Bc, 1);
        if (lane == 0) { Ae = 0x3F8000003F800000ull; Be = 0ull; }
        ull t = ffma2(Ae, s, Be);

        // regenerate 4 per-trial outputs; pairs are already {left,right}
        ulonglong2 o0, o1;
        t = ffma2(CA[0], t, CB[0]);  o0.x = t;
        t = ffma2(CA[1], t, CB[1]);  o0.y = t;
        t = ffma2(CA[2], t, CB[2]);  o1.x = t;
        t = ffma2(CA[3], t, CB[3]);  o1.y = t;

        const int ob = chunk * 64 + 2 * lane;   // ulonglong2 index (16B = 2 trials)
        op2[ob]     = o0;
        op2[ob + 1] = o1;

        // session state = lane31's state after trial 127
        s = __shfl_sync(FULLM, t, 31);
    }
}

extern "C" void kernel_launch(void* const* d_in, const int* in_sizes, int n_in,
                              void* d_out, int out_size) {
    const float* inp  = (const float*)d_in[0];   // (4096, 2048, 3) f32
    const float* araw = (const float*)d_in[1];   // (4,) f32
    const float* kv   = (const float*)d_in[2];   // (4,) f32
    float* out = (float*)d_out;                  // (4096, 2048, 2) f32

    // 4096 warps in 128-thread blocks -> 1024 blocks
    qvalue_kernel<<<1024, 128>>>(inp, araw, kv, out);
}